// round 1
// baseline (speedup 1.0000x reference)
#include <cuda_runtime.h>
#include <cstdint>

#define N_NODES 50000
#define N_EDGES 800000
#define FEAT    1024
#define EMB     128

// Scratch for h = x @ W^T  (25.6 MB) — __device__ global (no allocs allowed).
__device__ float g_h[(size_t)N_NODES * EMB];

// ---------------------------------------------------------------------------
// Kernel 1: zero the output (harness poisons d_out with 0xAA).
// ---------------------------------------------------------------------------
__global__ void zero_out_kernel(float4* __restrict__ out, int n4) {
    int i = blockIdx.x * blockDim.x + threadIdx.x;
    if (i < n4) out[i] = make_float4(0.f, 0.f, 0.f, 0.f);
}

// ---------------------------------------------------------------------------
// Kernel 2: SGEMM  h[n][e] = sum_k x[n][k] * w[e][k]
// Tiling: BM=128, BN=128, BK=16, 256 threads, each thread 8x8 micro-tile.
// ---------------------------------------------------------------------------
#define BM 128
#define BN 128
#define BK 16

__global__ __launch_bounds__(256, 2)
void gemm_xwT_kernel(const float* __restrict__ x, const float* __restrict__ w) {
    __shared__ float As[BK][BM + 4];   // [k][m], padded to break bank conflicts
    __shared__ float Bs[BK][BN + 4];   // [k][n]

    const int tid = threadIdx.x;
    const int m0  = blockIdx.x * BM;

    // micro-tile coordinates: 16x16 grid of threads, each covering 8x8 outputs
    const int tm = (tid >> 4) * 8;     // 0..120
    const int tn = (tid & 15) * 8;     // 0..120

    // global->shared load mapping: each thread moves 2 float4 of x and 2 of w
    const int lr = tid >> 1;           // row within tile 0..127
    const int lc = (tid & 1) * 8;      // k-offset within BK: 0 or 8

    float acc[8][8];
#pragma unroll
    for (int i = 0; i < 8; i++)
#pragma unroll
        for (int j = 0; j < 8; j++) acc[i][j] = 0.f;

    const int gxr = m0 + lr;           // global x row for this thread's loads
    const bool xrow_ok = (gxr < N_NODES);
    const float* xrow = x + (size_t)gxr * FEAT;
    const float* wrow = w + (size_t)lr  * FEAT;

    for (int k0 = 0; k0 < FEAT; k0 += BK) {
        // ---- load x tile (transposed into As[k][m]) ----
        float4 xa, xb;
        if (xrow_ok) {
            xa = *(const float4*)(xrow + k0 + lc);
            xb = *(const float4*)(xrow + k0 + lc + 4);
        } else {
            xa = make_float4(0.f, 0.f, 0.f, 0.f);
            xb = xa;
        }
        As[lc + 0][lr] = xa.x; As[lc + 1][lr] = xa.y;
        As[lc + 2][lr] = xa.z; As[lc + 3][lr] = xa.w;
        As[lc + 4][lr] = xb.x; As[lc + 5][lr] = xb.y;
        As[lc + 6][lr] = xb.z; As[lc + 7][lr] = xb.w;

        // ---- load w tile (transposed into Bs[k][n]) ----
        float4 wa = *(const float4*)(wrow + k0 + lc);
        float4 wb = *(const float4*)(wrow + k0 + lc + 4);
        Bs[lc + 0][lr] = wa.x; Bs[lc + 1][lr] = wa.y;
        Bs[lc + 2][lr] = wa.z; Bs[lc + 3][lr] = wa.w;
        Bs[lc + 4][lr] = wb.x; Bs[lc + 5][lr] = wb.y;
        Bs[lc + 6][lr] = wb.z; Bs[lc + 7][lr] = wb.w;

        __syncthreads();

#pragma unroll
        for (int kk = 0; kk < BK; kk++) {
            float4 a0 = *(const float4*)&As[kk][tm];
            float4 a1 = *(const float4*)&As[kk][tm + 4];
            float4 b0 = *(const float4*)&Bs[kk][tn];
            float4 b1 = *(const float4*)&Bs[kk][tn + 4];
            float a[8] = {a0.x, a0.y, a0.z, a0.w, a1.x, a1.y, a1.z, a1.w};
            float b[8] = {b0.x, b0.y, b0.z, b0.w, b1.x, b1.y, b1.z, b1.w};
#pragma unroll
            for (int i = 0; i < 8; i++)
#pragma unroll
                for (int j = 0; j < 8; j++)
                    acc[i][j] = fmaf(a[i], b[j], acc[i][j]);
        }
        __syncthreads();
    }

    // ---- store to g_h ----
#pragma unroll
    for (int i = 0; i < 8; i++) {
        int r = m0 + tm + i;
        if (r < N_NODES) {
            float4 v0 = make_float4(acc[i][0], acc[i][1], acc[i][2], acc[i][3]);
            float4 v1 = make_float4(acc[i][4], acc[i][5], acc[i][6], acc[i][7]);
            *(float4*)(g_h + (size_t)r * EMB + tn)     = v0;
            *(float4*)(g_h + (size_t)r * EMB + tn + 4) = v1;
        }
    }
}

// ---------------------------------------------------------------------------
// Kernel 3: COO scatter  out[row[e]] += vals[e] * h[col[e]]
// One warp per edge; each lane handles 4 embed dims via a single
// red.global.add.v4.f32 (vector fp32 reduction, sm_90+; no return trip).
// h (25.6 MB) fits in L2 -> gathers are L2-resident.
// ---------------------------------------------------------------------------
__global__ void spmm_scatter_kernel(const int*   __restrict__ row,
                                    const int*   __restrict__ col,
                                    const float* __restrict__ vals,
                                    float*       __restrict__ out) {
    const int lane   = threadIdx.x & 31;
    const int warp   = (blockIdx.x * blockDim.x + threadIdx.x) >> 5;
    const int nwarps = (gridDim.x * blockDim.x) >> 5;

    for (int e = warp; e < N_EDGES; e += nwarps) {
        const int   r = row[e];
        const int   c = col[e];
        const float v = vals[e];

        const float4 hv = __ldg((const float4*)(g_h + (size_t)c * EMB) + lane);
        float mx = v * hv.x, my = v * hv.y, mz = v * hv.z, mw = v * hv.w;

        float* dst = out + (size_t)r * EMB + lane * 4;
        asm volatile("red.global.add.v4.f32 [%0], {%1, %2, %3, %4};"
                     :: "l"(dst), "f"(mx), "f"(my), "f"(mz), "f"(mw)
                     : "memory");
    }
}

// ---------------------------------------------------------------------------
// Launch
// ---------------------------------------------------------------------------
extern "C" void kernel_launch(void* const* d_in, const int* in_sizes, int n_in,
                              void* d_out, int out_size) {
    const float* x    = (const float*)d_in[0];   // [50000, 1024]
    const float* w    = (const float*)d_in[1];   // [128, 1024]
    const int*   row  = (const int*)  d_in[2];   // [800000]
    const int*   col  = (const int*)  d_in[3];   // [800000]
    const float* vals = (const float*)d_in[4];   // [800000]
    float*       out  = (float*)d_out;           // [50000, 128]

    // 1) zero output (poisoned by harness)
    {
        int n4 = (N_NODES * EMB) / 4;
        zero_out_kernel<<<(n4 + 255) / 256, 256>>>((float4*)out, n4);
    }

    // 2) h = x @ W^T
    {
        int grid = (N_NODES + BM - 1) / BM;   // 391 blocks
        gemm_xwT_kernel<<<grid, 256>>>(x, w);
    }

    // 3) scatter-add over edges
    {
        // 2048 blocks * 8 warps = 16384 warps; ~49 edges per warp grid-stride
        spmm_scatter_kernel<<<2048, 256>>>(row, col, vals, out);
    }
}

// round 3
// speedup vs baseline: 1.2666x; 1.2666x over previous
#include <cuda_runtime.h>
#include <cstdint>

#define N_NODES 50000
#define N_EDGES 800000
#define FEAT    1024
#define EMB     128

// ---------------------------------------------------------------------------
// Device-global scratch (no allocs allowed)
// ---------------------------------------------------------------------------
__device__ float g_h[(size_t)N_NODES * EMB];          // h = x @ W^T   (25.6 MB)
__device__ float g_wh[(size_t)EMB * FEAT];            // W split hi (tf32 pattern)
__device__ float g_wl[(size_t)EMB * FEAT];            // W split lo
__device__ int   g_cnt[N_NODES];                      // degree counters
__device__ int   g_off[N_NODES + 1];                  // CSR offsets
__device__ int   g_part[128];                         // scan partials
__device__ int   g_ecol[N_EDGES];                     // bucketed cols
__device__ float g_eval[N_EDGES];                     // bucketed vals

// ---------------------------------------------------------------------------
// tf32 helpers (legacy mma.sync path — plain sm_80+ PTX, no 'a' features)
// ---------------------------------------------------------------------------
__device__ __forceinline__ float tf32_rna(float v) {
    uint32_t r;
    asm("cvt.rna.tf32.f32 %0, %1;" : "=r"(r) : "f"(v));
    return __uint_as_float(r);
}

__device__ __forceinline__ void mma8(float d[4], const uint32_t a[4],
                                     uint32_t b0, uint32_t b1) {
    asm volatile(
        "mma.sync.aligned.m16n8k8.row.col.f32.tf32.tf32.f32 "
        "{%0,%1,%2,%3}, {%4,%5,%6,%7}, {%8,%9}, {%0,%1,%2,%3};"
        : "+f"(d[0]), "+f"(d[1]), "+f"(d[2]), "+f"(d[3])
        : "r"(a[0]), "r"(a[1]), "r"(a[2]), "r"(a[3]), "r"(b0), "r"(b1));
}

// ---------------------------------------------------------------------------
// Kernel: split W once into tf32 hi/lo (reused by all GEMM CTAs)
// ---------------------------------------------------------------------------
__global__ void split_w_kernel(const float* __restrict__ w) {
    int i = blockIdx.x * blockDim.x + threadIdx.x;
    if (i < EMB * FEAT) {
        float v = w[i];
        float h = tf32_rna(v);
        g_wh[i] = h;
        g_wl[i] = tf32_rna(v - h);
    }
}

// ---------------------------------------------------------------------------
// GEMM: h = x @ W^T via mma.sync tf32, 3xTF32 split.
// CTA: 128 rows x 128 cols, K chunks of 32. 256 threads = 8 warps (4Mx2N),
// warp tile 32x64 (2 m-tiles x 8 n-tiles of m16n8k8).
// ---------------------------------------------------------------------------
#define PAD 36   // f32 row stride in smem: 36 mod 32 banks -> conflict-free frags
#define KC  32
#define NKIT (FEAT / KC)

__global__ __launch_bounds__(256)
void gemm_tf32_mma(const float* __restrict__ x) {
    extern __shared__ float sm[];
    float* axh = sm;                    // [128][PAD]
    float* axl = sm + 128 * PAD;
    float* swh = sm + 2 * 128 * PAD;
    float* swl = sm + 3 * 128 * PAD;

    const int tid  = threadIdx.x;
    const int m0   = blockIdx.x * 128;
    const int wid  = tid >> 5;
    const int lane = tid & 31;
    const int wm   = (wid & 3) * 32;    // warp M offset
    const int wn   = (wid >> 2) * 64;   // warp N offset
    const int g    = lane >> 2;         // groupID
    const int t    = lane & 3;          // threadID_in_group

    // global->smem mapping: thread covers one row, 16 k per iter
    const int lrow = tid >> 1;
    const int lk   = (tid & 1) * 16;
    const int gxr  = m0 + lrow;
    const bool xok = (gxr < N_NODES);
    const float* xrow  = x    + (size_t)(xok ? gxr : 0) * FEAT;
    const float* whrow = g_wh + (size_t)lrow * FEAT;
    const float* wlrow = g_wl + (size_t)lrow * FEAT;

    float acc[2][8][4];
#pragma unroll
    for (int mi = 0; mi < 2; mi++)
#pragma unroll
        for (int ni = 0; ni < 8; ni++)
#pragma unroll
            for (int j = 0; j < 4; j++) acc[mi][ni][j] = 0.f;

    float4 xb[4], whb[4], wlb[4];
    // prologue prefetch k0 = 0
#pragma unroll
    for (int j = 0; j < 4; j++) {
        xb[j]  = xok ? *(const float4*)(xrow + lk + j * 4)
                     : make_float4(0.f, 0.f, 0.f, 0.f);
        whb[j] = *(const float4*)(whrow + lk + j * 4);
        wlb[j] = *(const float4*)(wlrow + lk + j * 4);
    }

    for (int it = 0; it < NKIT; ++it) {
        __syncthreads();   // previous iter's frag reads finished

        // split x into tf32 hi/lo and store; copy pre-split w
        float* pxh = axh + lrow * PAD + lk;
        float* pxl = axl + lrow * PAD + lk;
        float* pwh = swh + lrow * PAD + lk;
        float* pwl = swl + lrow * PAD + lk;
#pragma unroll
        for (int j = 0; j < 4; j++) {
            float4 v = xb[j];
            float4 h4, l4;
            h4.x = tf32_rna(v.x); l4.x = tf32_rna(v.x - h4.x);
            h4.y = tf32_rna(v.y); l4.y = tf32_rna(v.y - h4.y);
            h4.z = tf32_rna(v.z); l4.z = tf32_rna(v.z - h4.z);
            h4.w = tf32_rna(v.w); l4.w = tf32_rna(v.w - h4.w);
            *(float4*)(pxh + j * 4) = h4;
            *(float4*)(pxl + j * 4) = l4;
            *(float4*)(pwh + j * 4) = whb[j];
            *(float4*)(pwl + j * 4) = wlb[j];
        }
        __syncthreads();

        // prefetch next chunk while MMAs execute
        if (it + 1 < NKIT) {
            const int k0 = (it + 1) * KC;
#pragma unroll
            for (int j = 0; j < 4; j++) {
                xb[j]  = xok ? *(const float4*)(xrow + k0 + lk + j * 4)
                             : make_float4(0.f, 0.f, 0.f, 0.f);
                whb[j] = *(const float4*)(whrow + k0 + lk + j * 4);
                wlb[j] = *(const float4*)(wlrow + k0 + lk + j * 4);
            }
        }

#pragma unroll
        for (int ks = 0; ks < 4; ks++) {
            const int k0 = ks * 8;
            uint32_t ah[2][4], al[2][4];
#pragma unroll
            for (int mi = 0; mi < 2; mi++) {
                const int r = wm + mi * 16;
                ah[mi][0] = __float_as_uint(axh[(r + g)     * PAD + k0 + t]);
                ah[mi][1] = __float_as_uint(axh[(r + g + 8) * PAD + k0 + t]);
                ah[mi][2] = __float_as_uint(axh[(r + g)     * PAD + k0 + t + 4]);
                ah[mi][3] = __float_as_uint(axh[(r + g + 8) * PAD + k0 + t + 4]);
                al[mi][0] = __float_as_uint(axl[(r + g)     * PAD + k0 + t]);
                al[mi][1] = __float_as_uint(axl[(r + g + 8) * PAD + k0 + t]);
                al[mi][2] = __float_as_uint(axl[(r + g)     * PAD + k0 + t + 4]);
                al[mi][3] = __float_as_uint(axl[(r + g + 8) * PAD + k0 + t + 4]);
            }
#pragma unroll
            for (int ni = 0; ni < 8; ni++) {
                const int n = wn + ni * 8;
                uint32_t bh0 = __float_as_uint(swh[(n + g) * PAD + k0 + t]);
                uint32_t bh1 = __float_as_uint(swh[(n + g) * PAD + k0 + t + 4]);
                uint32_t bl0 = __float_as_uint(swl[(n + g) * PAD + k0 + t]);
                uint32_t bl1 = __float_as_uint(swl[(n + g) * PAD + k0 + t + 4]);
#pragma unroll
                for (int mi = 0; mi < 2; mi++) {
                    mma8(acc[mi][ni], ah[mi], bh0, bh1);   // xh*wh
                    mma8(acc[mi][ni], ah[mi], bl0, bl1);   // xh*wl
                    mma8(acc[mi][ni], al[mi], bh0, bh1);   // xl*wh
                }
            }
        }
    }

    // epilogue: C frag (g,2t),(g,2t+1) / (g+8,2t),(g+8,2t+1)
#pragma unroll
    for (int mi = 0; mi < 2; mi++) {
#pragma unroll
        for (int ni = 0; ni < 8; ni++) {
            const int r = m0 + wm + mi * 16 + g;
            const int c = wn + ni * 8 + 2 * t;
            if (r < N_NODES)
                *(float2*)(g_h + (size_t)r * EMB + c) =
                    make_float2(acc[mi][ni][0], acc[mi][ni][1]);
            if (r + 8 < N_NODES)
                *(float2*)(g_h + (size_t)(r + 8) * EMB + c) =
                    make_float2(acc[mi][ni][2], acc[mi][ni][3]);
        }
    }
}

// ---------------------------------------------------------------------------
// CSR build: zero -> hist -> scan (3 kernels) -> bucket
// ---------------------------------------------------------------------------
__global__ void zero_cnt_kernel() {
    int i = blockIdx.x * blockDim.x + threadIdx.x;
    if (i < N_NODES) g_cnt[i] = 0;
}

__global__ void hist_kernel(const int* __restrict__ row) {
    int e = blockIdx.x * blockDim.x + threadIdx.x;
    if (e < N_EDGES) atomicAdd(&g_cnt[row[e]], 1);
}

#define SCAN_B 512
#define SCAN_NB ((N_NODES + SCAN_B - 1) / SCAN_B)   // 98

__global__ void scan1_kernel() {
    __shared__ int s[SCAN_B];
    int i = blockIdx.x * SCAN_B + threadIdx.x;
    int v = (i < N_NODES) ? g_cnt[i] : 0;
    s[threadIdx.x] = v;
    __syncthreads();
#pragma unroll
    for (int d = 1; d < SCAN_B; d <<= 1) {
        int tmp = (threadIdx.x >= d) ? s[threadIdx.x - d] : 0;
        __syncthreads();
        s[threadIdx.x] += tmp;
        __syncthreads();
    }
    if (i < N_NODES) g_off[i] = s[threadIdx.x] - v;   // exclusive within block
    if (threadIdx.x == SCAN_B - 1) g_part[blockIdx.x] = s[SCAN_B - 1];
}

__global__ void scan2_kernel() {
    __shared__ int s[128];
    int tid = threadIdx.x;
    int v = (tid < SCAN_NB) ? g_part[tid] : 0;
    s[tid] = v;
    __syncthreads();
#pragma unroll
    for (int d = 1; d < 128; d <<= 1) {
        int tmp = (tid >= d) ? s[tid - d] : 0;
        __syncthreads();
        s[tid] += tmp;
        __syncthreads();
    }
    if (tid < SCAN_NB) g_part[tid] = s[tid] - v;      // exclusive block offsets
    if (tid == 0) g_off[N_NODES] = N_EDGES;
}

__global__ void scan3_kernel() {
    int i = blockIdx.x * SCAN_B + threadIdx.x;
    if (i < N_NODES) {
        g_off[i] += g_part[blockIdx.x];
        g_cnt[i] = 0;   // reset fill counters for bucket pass
    }
}

__global__ void bucket_kernel(const int* __restrict__ row,
                              const int* __restrict__ col,
                              const float* __restrict__ vals) {
    int e = blockIdx.x * blockDim.x + threadIdx.x;
    if (e < N_EDGES) {
        int r = row[e];
        int pos = g_off[r] + atomicAdd(&g_cnt[r], 1);
        g_ecol[pos] = col[e];
        g_eval[pos] = vals[e];
    }
}

// ---------------------------------------------------------------------------
// Gather: one warp per destination node; atomic-free, writes out once.
// ---------------------------------------------------------------------------
__global__ void gather_kernel(float* __restrict__ out) {
    const int lane = threadIdx.x & 31;
    const int node = (blockIdx.x * blockDim.x + threadIdx.x) >> 5;
    if (node >= N_NODES) return;

    const int beg = g_off[node];
    const int end = g_off[node + 1];

    float4 acc = make_float4(0.f, 0.f, 0.f, 0.f);

    if (beg < end) {
        int   c = g_ecol[beg];
        float v = g_eval[beg];
        for (int e = beg; e < end; e++) {
            int cn = 0; float vn = 0.f;
            if (e + 1 < end) { cn = g_ecol[e + 1]; vn = g_eval[e + 1]; }
            const float4 hv = __ldg((const float4*)(g_h + (size_t)c * EMB) + lane);
            acc.x = fmaf(v, hv.x, acc.x);
            acc.y = fmaf(v, hv.y, acc.y);
            acc.z = fmaf(v, hv.z, acc.z);
            acc.w = fmaf(v, hv.w, acc.w);
            c = cn; v = vn;
        }
    }
    *((float4*)(out + (size_t)node * EMB) + lane) = acc;
}

// ---------------------------------------------------------------------------
// Launch
// ---------------------------------------------------------------------------
#define SM_TOTAL (4 * 128 * PAD * 4)   // 73,728 bytes dynamic smem

extern "C" void kernel_launch(void* const* d_in, const int* in_sizes, int n_in,
                              void* d_out, int out_size) {
    const float* x    = (const float*)d_in[0];
    const float* w    = (const float*)d_in[1];
    const int*   row  = (const int*)  d_in[2];
    const int*   col  = (const int*)  d_in[3];
    const float* vals = (const float*)d_in[4];
    float*       out  = (float*)d_out;

    // --- CSR build (independent of GEMM) ---
    zero_cnt_kernel<<<(N_NODES + 255) / 256, 256>>>();
    hist_kernel<<<(N_EDGES + 255) / 256, 256>>>(row);
    scan1_kernel<<<SCAN_NB, SCAN_B>>>();
    scan2_kernel<<<1, 128>>>();
    scan3_kernel<<<SCAN_NB, SCAN_B>>>();
    bucket_kernel<<<(N_EDGES + 255) / 256, 256>>>(row, col, vals);

    // --- GEMM: h = x @ W^T (3xTF32 mma.sync) ---
    split_w_kernel<<<(EMB * FEAT + 255) / 256, 256>>>(w);
    cudaFuncSetAttribute(gemm_tf32_mma,
                         cudaFuncAttributeMaxDynamicSharedMemorySize, SM_TOTAL);
    gemm_tf32_mma<<<(N_NODES + 127) / 128, 256, SM_TOTAL>>>(x);

    // --- atomic-free gather (writes every out row; no memset needed) ---
    gather_kernel<<<(N_NODES * 32 + 255) / 256, 256>>>(out);
}

// round 4
// speedup vs baseline: 1.8916x; 1.4934x over previous
#include <cuda_runtime.h>
#include <cuda_fp16.h>
#include <cstdint>

#define N_NODES 50000
#define N_EDGES 800000
#define FEAT    1024
#define EMB     128

// ---------------------------------------------------------------------------
// Device-global scratch (no allocs allowed)
// ---------------------------------------------------------------------------
__device__ float  g_h[(size_t)N_NODES * EMB];     // h = x @ W^T   (25.6 MB)
__device__ __half g_wh16[(size_t)EMB * FEAT];     // W split hi (fp16)
__device__ __half g_wl16[(size_t)EMB * FEAT];     // W split lo (fp16)
__device__ int    g_cnt[N_NODES];                 // degree counters
__device__ int    g_off[N_NODES + 1];             // CSR offsets
__device__ int    g_part[128];                    // scan partials
__device__ int2   g_edge[N_EDGES];                // bucketed (col, val-bits)

// ---------------------------------------------------------------------------
// fp16 split helpers
// ---------------------------------------------------------------------------
__device__ __forceinline__ void split16(float v, __half& hi, __half& lo) {
    hi = __float2half_rn(v);
    lo = __float2half_rn(v - __half2float(hi));
}

// mma.sync m16n8k16 f16 -> f32
__device__ __forceinline__ void mma16(float d[4], const uint32_t a[4],
                                      uint32_t b0, uint32_t b1) {
    asm volatile(
        "mma.sync.aligned.m16n8k16.row.col.f32.f16.f16.f32 "
        "{%0,%1,%2,%3}, {%4,%5,%6,%7}, {%8,%9}, {%0,%1,%2,%3};"
        : "+f"(d[0]), "+f"(d[1]), "+f"(d[2]), "+f"(d[3])
        : "r"(a[0]), "r"(a[1]), "r"(a[2]), "r"(a[3]), "r"(b0), "r"(b1));
}

// ---------------------------------------------------------------------------
// Kernel: split W once into fp16 hi/lo
// ---------------------------------------------------------------------------
__global__ void split_w_kernel(const float* __restrict__ w) {
    int i = blockIdx.x * blockDim.x + threadIdx.x;
    if (i < EMB * FEAT) {
        __half h, l;
        split16(w[i], h, l);
        g_wh16[i] = h;
        g_wl16[i] = l;
    }
}

// ---------------------------------------------------------------------------
// GEMM: h = x @ W^T via mma.sync fp16 (3xFP16 split).
// CTA: 128x128, K chunks of 32. 256 thr = 8 warps (4M x 2N), warp tile 32x64.
// ---------------------------------------------------------------------------
#define SH  40               // half-elements row stride in smem (conflict-free)
#define KC  32
#define NKIT (FEAT / KC)

__global__ __launch_bounds__(256)
void gemm_fp16_mma(const float* __restrict__ x) {
    __shared__ __half axh[128 * SH];
    __shared__ __half axl[128 * SH];
    __shared__ __half swh[128 * SH];
    __shared__ __half swl[128 * SH];

    const int tid  = threadIdx.x;
    const int m0   = blockIdx.x * 128;
    const int wid  = tid >> 5;
    const int lane = tid & 31;
    const int wm   = (wid & 3) * 32;    // warp M offset
    const int wn   = (wid >> 2) * 64;   // warp N offset
    const int g    = lane >> 2;
    const int t    = lane & 3;

    // global->smem mapping: thread covers one row, 16 k-elems per chunk
    const int lrow = tid >> 1;
    const int lk   = (tid & 1) * 16;
    const int gxr  = m0 + lrow;
    const bool xok = (gxr < N_NODES);
    const float* xrow = x + (size_t)(xok ? gxr : 0) * FEAT;
    const __half* whrow = g_wh16 + (size_t)lrow * FEAT;
    const __half* wlrow = g_wl16 + (size_t)lrow * FEAT;

    float acc[2][8][4];
#pragma unroll
    for (int mi = 0; mi < 2; mi++)
#pragma unroll
        for (int ni = 0; ni < 8; ni++)
#pragma unroll
            for (int j = 0; j < 4; j++) acc[mi][ni][j] = 0.f;

    float4 xb[4];          // 16 floats of x
    uint4  whb[2], wlb[2]; // 16+16 halves of pre-split w

    // ---- prologue prefetch: chunk 0 ----
#pragma unroll
    for (int j = 0; j < 4; j++)
        xb[j] = xok ? *(const float4*)(xrow + lk + j * 4)
                    : make_float4(0.f, 0.f, 0.f, 0.f);
    whb[0] = *(const uint4*)(whrow + lk);
    whb[1] = *(const uint4*)(whrow + lk + 8);
    wlb[0] = *(const uint4*)(wlrow + lk);
    wlb[1] = *(const uint4*)(wlrow + lk + 8);

    for (int it = 0; it < NKIT; ++it) {
        __syncthreads();   // previous iter's frag reads done

        // split x -> fp16 hi/lo, store tiles; store pre-split w
        {
            __half h[16], l[16];
            const float* xf = (const float*)xb;
#pragma unroll
            for (int j = 0; j < 16; j++) split16(xf[j], h[j], l[j]);
            __half* pxh = axh + lrow * SH + lk;
            __half* pxl = axl + lrow * SH + lk;
            *(uint4*)(pxh)     = *(const uint4*)(h);
            *(uint4*)(pxh + 8) = *(const uint4*)(h + 8);
            *(uint4*)(pxl)     = *(const uint4*)(l);
            *(uint4*)(pxl + 8) = *(const uint4*)(l + 8);
            __half* pwh = swh + lrow * SH + lk;
            __half* pwl = swl + lrow * SH + lk;
            *(uint4*)(pwh)     = whb[0];
            *(uint4*)(pwh + 8) = whb[1];
            *(uint4*)(pwl)     = wlb[0];
            *(uint4*)(pwl + 8) = wlb[1];
        }
        __syncthreads();

        // prefetch next chunk (overlaps with MMA section)
        if (it + 1 < NKIT) {
            const int k0 = (it + 1) * KC;
#pragma unroll
            for (int j = 0; j < 4; j++)
                xb[j] = xok ? *(const float4*)(xrow + k0 + lk + j * 4)
                            : make_float4(0.f, 0.f, 0.f, 0.f);
            whb[0] = *(const uint4*)(whrow + k0 + lk);
            whb[1] = *(const uint4*)(whrow + k0 + lk + 8);
            wlb[0] = *(const uint4*)(wlrow + k0 + lk);
            wlb[1] = *(const uint4*)(wlrow + k0 + lk + 8);
        }

        // 2 k-steps of k=16
#pragma unroll
        for (int ks = 0; ks < 2; ks++) {
            const int k0 = ks * 16;
            uint32_t ah[2][4], al[2][4];
#pragma unroll
            for (int mi = 0; mi < 2; mi++) {
                const int r = wm + mi * 16;
                const __half* bh = axh + k0 + 2 * t;
                const __half* bl = axl + k0 + 2 * t;
                ah[mi][0] = *(const uint32_t*)(bh + (r + g)     * SH);
                ah[mi][1] = *(const uint32_t*)(bh + (r + g + 8) * SH);
                ah[mi][2] = *(const uint32_t*)(bh + (r + g)     * SH + 8);
                ah[mi][3] = *(const uint32_t*)(bh + (r + g + 8) * SH + 8);
                al[mi][0] = *(const uint32_t*)(bl + (r + g)     * SH);
                al[mi][1] = *(const uint32_t*)(bl + (r + g + 8) * SH);
                al[mi][2] = *(const uint32_t*)(bl + (r + g)     * SH + 8);
                al[mi][3] = *(const uint32_t*)(bl + (r + g + 8) * SH + 8);
            }
#pragma unroll
            for (int ni = 0; ni < 8; ni++) {
                const int n = wn + ni * 8 + g;
                uint32_t bh0 = *(const uint32_t*)(swh + n * SH + k0 + 2 * t);
                uint32_t bh1 = *(const uint32_t*)(swh + n * SH + k0 + 2 * t + 8);
                uint32_t bl0 = *(const uint32_t*)(swl + n * SH + k0 + 2 * t);
                uint32_t bl1 = *(const uint32_t*)(swl + n * SH + k0 + 2 * t + 8);
#pragma unroll
                for (int mi = 0; mi < 2; mi++) {
                    mma16(acc[mi][ni], ah[mi], bh0, bh1);   // xh*wh
                    mma16(acc[mi][ni], ah[mi], bl0, bl1);   // xh*wl
                    mma16(acc[mi][ni], al[mi], bh0, bh1);   // xl*wh
                }
            }
        }
    }

    // epilogue
#pragma unroll
    for (int mi = 0; mi < 2; mi++) {
#pragma unroll
        for (int ni = 0; ni < 8; ni++) {
            const int r = m0 + wm + mi * 16 + g;
            const int c = wn + ni * 8 + 2 * t;
            if (r < N_NODES)
                *(float2*)(g_h + (size_t)r * EMB + c) =
                    make_float2(acc[mi][ni][0], acc[mi][ni][1]);
            if (r + 8 < N_NODES)
                *(float2*)(g_h + (size_t)(r + 8) * EMB + c) =
                    make_float2(acc[mi][ni][2], acc[mi][ni][3]);
        }
    }
}

// ---------------------------------------------------------------------------
// CSR build: zero -> hist -> scan x3 -> bucket
// ---------------------------------------------------------------------------
__global__ void zero_cnt_kernel() {
    int i = blockIdx.x * blockDim.x + threadIdx.x;
    if (i < N_NODES) g_cnt[i] = 0;
}

__global__ void hist_kernel(const int* __restrict__ row) {
    int e = blockIdx.x * blockDim.x + threadIdx.x;
    if (e < N_EDGES) atomicAdd(&g_cnt[row[e]], 1);
}

#define SCAN_B 512
#define SCAN_NB ((N_NODES + SCAN_B - 1) / SCAN_B)   // 98

__global__ void scan1_kernel() {
    __shared__ int s[SCAN_B];
    int i = blockIdx.x * SCAN_B + threadIdx.x;
    int v = (i < N_NODES) ? g_cnt[i] : 0;
    s[threadIdx.x] = v;
    __syncthreads();
#pragma unroll
    for (int d = 1; d < SCAN_B; d <<= 1) {
        int tmp = (threadIdx.x >= d) ? s[threadIdx.x - d] : 0;
        __syncthreads();
        s[threadIdx.x] += tmp;
        __syncthreads();
    }
    if (i < N_NODES) g_off[i] = s[threadIdx.x] - v;
    if (threadIdx.x == SCAN_B - 1) g_part[blockIdx.x] = s[SCAN_B - 1];
}

__global__ void scan2_kernel() {
    __shared__ int s[128];
    int tid = threadIdx.x;
    int v = (tid < SCAN_NB) ? g_part[tid] : 0;
    s[tid] = v;
    __syncthreads();
#pragma unroll
    for (int d = 1; d < 128; d <<= 1) {
        int tmp = (tid >= d) ? s[tid - d] : 0;
        __syncthreads();
        s[tid] += tmp;
        __syncthreads();
    }
    if (tid < SCAN_NB) g_part[tid] = s[tid] - v;
    if (tid == 0) g_off[N_NODES] = N_EDGES;
}

__global__ void scan3_kernel() {
    int i = blockIdx.x * SCAN_B + threadIdx.x;
    if (i < N_NODES) {
        g_off[i] += g_part[blockIdx.x];
        g_cnt[i] = 0;
    }
}

__global__ void bucket_kernel(const int* __restrict__ row,
                              const int* __restrict__ col,
                              const float* __restrict__ vals) {
    int e = blockIdx.x * blockDim.x + threadIdx.x;
    if (e < N_EDGES) {
        int r = row[e];
        int pos = g_off[r] + atomicAdd(&g_cnt[r], 1);
        g_edge[pos] = make_int2(col[e], __float_as_int(vals[e]));
    }
}

// ---------------------------------------------------------------------------
// Gather: one warp per destination node; atomic-free.
// ---------------------------------------------------------------------------
__global__ void gather_kernel(float* __restrict__ out) {
    const int lane = threadIdx.x & 31;
    const int node = (blockIdx.x * blockDim.x + threadIdx.x) >> 5;
    if (node >= N_NODES) return;

    const int beg = g_off[node];
    const int end = g_off[node + 1];

    float4 acc = make_float4(0.f, 0.f, 0.f, 0.f);
    for (int e = beg; e < end; e++) {
        const int2 ev = g_edge[e];
        const float v = __int_as_float(ev.y);
        const float4 hv = __ldg((const float4*)(g_h + (size_t)ev.x * EMB) + lane);
        acc.x = fmaf(v, hv.x, acc.x);
        acc.y = fmaf(v, hv.y, acc.y);
        acc.z = fmaf(v, hv.z, acc.z);
        acc.w = fmaf(v, hv.w, acc.w);
    }
    *((float4*)(out + (size_t)node * EMB) + lane) = acc;
}

// ---------------------------------------------------------------------------
// Launch
// ---------------------------------------------------------------------------
extern "C" void kernel_launch(void* const* d_in, const int* in_sizes, int n_in,
                              void* d_out, int out_size) {
    const float* x    = (const float*)d_in[0];
    const float* w    = (const float*)d_in[1];
    const int*   row  = (const int*)  d_in[2];
    const int*   col  = (const int*)  d_in[3];
    const float* vals = (const float*)d_in[4];
    float*       out  = (float*)d_out;

    // --- CSR build ---
    zero_cnt_kernel<<<(N_NODES + 255) / 256, 256>>>();
    hist_kernel<<<(N_EDGES + 255) / 256, 256>>>(row);
    scan1_kernel<<<SCAN_NB, SCAN_B>>>();
    scan2_kernel<<<1, 128>>>();
    scan3_kernel<<<SCAN_NB, SCAN_B>>>();
    bucket_kernel<<<(N_EDGES + 255) / 256, 256>>>(row, col, vals);

    // --- GEMM: h = x @ W^T (3xFP16 mma.sync) ---
    split_w_kernel<<<(EMB * FEAT + 255) / 256, 256>>>(w);
    gemm_fp16_mma<<<(N_NODES + 127) / 128, 256>>>(x);

    // --- atomic-free gather ---
    gather_kernel<<<(N_NODES * 32 + 255) / 256, 256>>>(out);
}